// round 1
// baseline (speedup 1.0000x reference)
#include <cuda_runtime.h>
#include <math.h>

#define NN 16384
#define DD 512
#define OO 512
#define MINN 1e-15f

#define BM 64
#define BN 64
#define BK 16

// Scratch for precomputed per-row stats (no allocations allowed).
__device__ float g_x2[NN];
__device__ float g_p2[OO];
__device__ float g_pa[OO];
__device__ float g_anorm[OO];
__device__ float g_escale[OO];

__device__ __forceinline__ float warp_sum(float v) {
#pragma unroll
    for (int s = 16; s > 0; s >>= 1) v += __shfl_xor_sync(0xffffffffu, v, s);
    return v;
}

// ---------------- per-O stats: ||p||^2, <p,a>, ||a||, exp(scale) ----------------
__global__ void stats_o(const float* __restrict__ P, const float* __restrict__ A,
                        const float* __restrict__ S) {
    int o = blockIdx.x;
    int t = threadIdx.x;  // 128 threads, DD/4 = 128 float4 per row
    const float4* p4 = reinterpret_cast<const float4*>(P + (size_t)o * DD);
    const float4* a4 = reinterpret_cast<const float4*>(A + (size_t)o * DD);
    float4 pv = p4[t], av = a4[t];
    float sp2 = pv.x * pv.x + pv.y * pv.y + pv.z * pv.z + pv.w * pv.w;
    float spa = pv.x * av.x + pv.y * av.y + pv.z * av.z + pv.w * av.w;
    float sa2 = av.x * av.x + av.y * av.y + av.z * av.z + av.w * av.w;
    sp2 = warp_sum(sp2);
    spa = warp_sum(spa);
    sa2 = warp_sum(sa2);
    __shared__ float sm[3][4];
    int w = t >> 5, l = t & 31;
    if (l == 0) { sm[0][w] = sp2; sm[1][w] = spa; sm[2][w] = sa2; }
    __syncthreads();
    if (t == 0) {
        float tp2 = sm[0][0] + sm[0][1] + sm[0][2] + sm[0][3];
        float tpa = sm[1][0] + sm[1][1] + sm[1][2] + sm[1][3];
        float ta2 = sm[2][0] + sm[2][1] + sm[2][2] + sm[2][3];
        g_p2[o] = tp2;
        g_pa[o] = tpa;
        g_anorm[o] = fmaxf(sqrtf(ta2), MINN);
        g_escale[o] = expf(S[o]);
    }
}

// ---------------- per-row ||x||^2 (one warp per row) ----------------
__global__ void stats_x(const float* __restrict__ X) {
    int warp = (blockIdx.x * blockDim.x + threadIdx.x) >> 5;
    int lane = threadIdx.x & 31;
    if (warp >= NN) return;
    const float4* x4 = reinterpret_cast<const float4*>(X + (size_t)warp * DD);
    float s = 0.f;
#pragma unroll
    for (int j = 0; j < 4; j++) {
        float4 v = x4[lane + 32 * j];
        s += v.x * v.x + v.y * v.y + v.z * v.z + v.w * v.w;
    }
    s = warp_sum(s);
    if (lane == 0) g_x2[warp] = s;
}

// ---------------- packed f32x2 helpers (FFMA2 path, PTX-only) ----------------
__device__ __forceinline__ unsigned long long pk2(float lo, float hi) {
    unsigned long long r;
    asm("mov.b64 %0, {%1, %2};" : "=l"(r) : "f"(lo), "f"(hi));
    return r;
}
__device__ __forceinline__ void fma2(unsigned long long& d, unsigned long long a,
                                     unsigned long long b) {
    asm("fma.rn.f32x2 %0, %1, %2, %0;" : "+l"(d) : "l"(a), "l"(b));
}
__device__ __forceinline__ float2 upk2(unsigned long long v) {
    float2 r;
    asm("mov.b64 {%0, %1}, %2;" : "=f"(r.x), "=f"(r.y) : "l"(v));
    return r;
}

// ---------------- main fused dual-GEMM + Mobius epilogue ----------------
__global__ __launch_bounds__(256) void mobius_main(
    const float* __restrict__ X, const float* __restrict__ P,
    const float* __restrict__ A, float* __restrict__ out) {
    __shared__ float xs[BK][BM + 4];
    __shared__ float ps[BK][BN + 4];
    __shared__ float as_[BK][BN + 4];

    int tid = threadIdx.x;
    int tx = tid & 15, ty = tid >> 4;           // 16x16 thread grid, 4x4 microtile
    int m0 = blockIdx.y * BM, n0 = blockIdx.x * BN;
    int lr = tid >> 2;                           // load row 0..63
    int lc = (tid & 3) << 2;                     // load col {0,4,8,12}

    const float* xg = X + (size_t)(m0 + lr) * DD + lc;
    const float* pg = P + (size_t)(n0 + lr) * DD + lc;
    const float* ag = A + (size_t)(n0 + lr) * DD + lc;

    unsigned long long accP[4][2] = {};  // xp accumulators, packed pairs over n
    unsigned long long accA[4][2] = {};  // xa accumulators

    for (int k0 = 0; k0 < DD; k0 += BK) {
        float4 xv = *reinterpret_cast<const float4*>(xg + k0);
        float4 pv = *reinterpret_cast<const float4*>(pg + k0);
        float4 av = *reinterpret_cast<const float4*>(ag + k0);
        if (k0) __syncthreads();
        xs[lc + 0][lr] = xv.x; xs[lc + 1][lr] = xv.y;
        xs[lc + 2][lr] = xv.z; xs[lc + 3][lr] = xv.w;
        ps[lc + 0][lr] = pv.x; ps[lc + 1][lr] = pv.y;
        ps[lc + 2][lr] = pv.z; ps[lc + 3][lr] = pv.w;
        as_[lc + 0][lr] = av.x; as_[lc + 1][lr] = av.y;
        as_[lc + 2][lr] = av.z; as_[lc + 3][lr] = av.w;
        __syncthreads();
#pragma unroll
        for (int k = 0; k < BK; k++) {
            float4 xr = *reinterpret_cast<const float4*>(&xs[k][ty << 2]);
            float4 pr = *reinterpret_cast<const float4*>(&ps[k][tx << 2]);
            float4 ar = *reinterpret_cast<const float4*>(&as_[k][tx << 2]);
            unsigned long long p01 = pk2(pr.x, pr.y), p23 = pk2(pr.z, pr.w);
            unsigned long long a01 = pk2(ar.x, ar.y), a23 = pk2(ar.z, ar.w);
            float xi[4] = {xr.x, xr.y, xr.z, xr.w};
#pragma unroll
            for (int i = 0; i < 4; i++) {
                unsigned long long xd = pk2(xi[i], xi[i]);
                fma2(accP[i][0], xd, p01);
                fma2(accP[i][1], xd, p23);
                fma2(accA[i][0], xd, a01);
                fma2(accA[i][1], xd, a23);
            }
        }
    }

    // ---- epilogue: Mobius dist2plane (c = 1, sqrt_c = 1) ----
    float x2r[4];
#pragma unroll
    for (int i = 0; i < 4; i++) x2r[i] = g_x2[m0 + (ty << 2) + i];
    int nb = n0 + (tx << 2);
    float p2c[4], pac[4], anc[4], esc[4];
#pragma unroll
    for (int j = 0; j < 4; j++) {
        p2c[j] = g_p2[nb + j];
        pac[j] = g_pa[nb + j];
        anc[j] = g_anorm[nb + j];
        esc[j] = g_escale[nb + j];
    }
#pragma unroll
    for (int i = 0; i < 4; i++) {
        float2 xp01 = upk2(accP[i][0]), xp23 = upk2(accP[i][1]);
        float2 xa01 = upk2(accA[i][0]), xa23 = upk2(accA[i][1]);
        float xpv[4] = {xp01.x, xp01.y, xp23.x, xp23.y};
        float xav[4] = {xa01.x, xa01.y, xa23.x, xa23.y};
        float res[4];
        float x2 = x2r[i];
#pragma unroll
        for (int j = 0; j < 4; j++) {
            float xp = xpv[j], xa = xav[j];
            float Ac = 1.f - 2.f * xp + x2;          // A = 1 + 2c<x,-p> + c||x||^2
            float B = 1.f - p2c[j];                  // B = 1 - c||p||^2
            float Dn = fmaxf(1.f - 2.f * xp + p2c[j] * x2, MINN);
            float dn2 = Ac * Ac * p2c[j] - 2.f * Ac * B * xp + B * B * x2;
            float dnorm2 = fmaxf(dn2 / (Dn * Dn), MINN);
            float sc = (-Ac * pac[j] + B * xa) / Dn; // <diff, a>
            float denom = fmaxf((1.f - dnorm2) * anc[j], MINN);
            res[j] = asinhf(2.f * sc / denom) * esc[j];
        }
        *reinterpret_cast<float4*>(out + (size_t)(m0 + (ty << 2) + i) * OO + nb) =
            make_float4(res[0], res[1], res[2], res[3]);
    }
}

extern "C" void kernel_launch(void* const* d_in, const int* in_sizes, int n_in,
                              void* d_out, int out_size) {
    const float* x = (const float*)d_in[0];      // [N, D]
    const float* p = (const float*)d_in[1];      // [O, D]
    const float* a = (const float*)d_in[2];      // [O, D]
    const float* s = (const float*)d_in[3];      // [O]
    float* out = (float*)d_out;                  // [N, O]

    stats_o<<<OO, 128>>>(p, a, s);
    stats_x<<<(NN * 32) / 256, 256>>>(x);
    dim3 grid(OO / BN, NN / BM);
    mobius_main<<<grid, 256>>>(x, p, a, out);
}